// round 2
// baseline (speedup 1.0000x reference)
#include <cuda_runtime.h>
#include <cstdint>

#define BATCH 2048
#define DIN 64
#define HID 512
#define G4 2048
#define KENC 576
#define KDEC 512
#define TIN 336
#define TOUT 96

#define BM 256
#define BN 128
#define BKT 16
#define SLDA 20

// ---------- device scratch (no allocation allowed) ----------
__device__ float g_Wenc[G4 * KENC];
__device__ float g_benc[G4];
__device__ float g_Wdec0[G4 * KDEC];
__device__ float g_bdec0[G4];
__device__ float g_Wdec[G4 * KDEC];
__device__ float g_bdec[G4];
__device__ float g_linWt[DIN * HID];
__device__ float g_h0[BATCH * HID];
__device__ float g_h1[BATCH * HID];
__device__ float g_c[BATCH * HID];
__device__ float g_Hdec[(size_t)TOUT * BATCH * HID];

// ---------- helpers ----------
__device__ __forceinline__ float to_tf32(float x) {
    uint32_t u; asm("cvt.rna.tf32.f32 %0, %1;" : "=r"(u) : "f"(x));
    return __uint_as_float(u);
}
__device__ __forceinline__ float rcp_fast(float x) {
    float y; asm("rcp.approx.f32 %0, %1;" : "=f"(y) : "f"(x)); return y;
}
__device__ __forceinline__ float sigmoid_f(float x) { return rcp_fast(1.0f + __expf(-x)); }
__device__ __forceinline__ float tanh_f(float x) { return 1.0f - 2.0f * rcp_fast(1.0f + __expf(2.0f * x)); }

__device__ __forceinline__ void mma_tf32(float* c, const uint32_t* a, const uint32_t* b) {
    asm volatile(
        "mma.sync.aligned.m16n8k8.row.col.f32.tf32.tf32.f32 "
        "{%0,%1,%2,%3}, {%4,%5,%6,%7}, {%8,%9}, {%0,%1,%2,%3};"
        : "+f"(c[0]), "+f"(c[1]), "+f"(c[2]), "+f"(c[3])
        : "r"(a[0]), "r"(a[1]), "r"(a[2]), "r"(a[3]), "r"(b[0]), "r"(b[1]));
}

// ---------- weight prep: gate interleave + decoder feedback fusion ----------
// interleaved row n = 4*u + gate  <->  original row r = gate*HID + u
__global__ void prep_weights(const float* __restrict__ eWih, const float* __restrict__ eWhh,
                             const float* __restrict__ ebih, const float* __restrict__ ebhh,
                             const float* __restrict__ dWih, const float* __restrict__ dWhh,
                             const float* __restrict__ dbih, const float* __restrict__ dbhh,
                             const float* __restrict__ linW, const float* __restrict__ linb) {
    __shared__ float wih[DIN];
    const int n = blockIdx.x;
    const int u = n >> 2, g = n & 3;
    const int r = g * HID + u;

    for (int d = threadIdx.x; d < DIN; d += blockDim.x) wih[d] = dWih[r * DIN + d];
    __syncthreads();

    for (int k = threadIdx.x; k < KENC; k += blockDim.x) {
        float v = (k < DIN) ? eWih[r * DIN + k] : eWhh[r * HID + (k - DIN)];
        g_Wenc[n * KENC + k] = to_tf32(v);
    }
    for (int k = threadIdx.x; k < KDEC; k += blockDim.x) {
        float w0 = dWhh[r * HID + k];
        g_Wdec0[n * KDEC + k] = to_tf32(w0);
        float acc = w0;
#pragma unroll 8
        for (int d = 0; d < DIN; d++) acc += wih[d] * linW[d * HID + k];
        g_Wdec[n * KDEC + k] = to_tf32(acc);
    }
    if (n < DIN) {
        for (int k = threadIdx.x; k < HID; k += blockDim.x)
            g_linWt[n * HID + k] = to_tf32(linW[n * HID + k]);
    }
    if (threadIdx.x == 0) {
        g_benc[n] = ebih[r] + ebhh[r];
        float bd = dbih[r] + dbhh[r];
        g_bdec0[n] = bd;
        float acc = bd;
        for (int d = 0; d < DIN; d++) acc += wih[d] * linb[d];
        g_bdec[n] = acc;
    }
}

__global__ void init_state() {
    int i = blockIdx.x * blockDim.x + threadIdx.x;
    if (i < BATCH * HID) { g_h0[i] = 0.0f; g_c[i] = 0.0f; }
}

// ---------- fused per-step GEMM + LSTM cell ----------
template <int K, bool HAS_X>
__global__ __launch_bounds__(256, 1)
void lstm_step(const float* __restrict__ x, int hsel, int wsel, int dec_t) {
    __shared__ float As[BM][SLDA];
    __shared__ float Bs[BN][SLDA];

    const float* __restrict__ hin  = hsel ? g_h1 : g_h0;
    float* __restrict__       hout = hsel ? g_h0 : g_h1;
    const float* __restrict__ W    = (wsel == 0) ? g_Wenc : (wsel == 1 ? g_Wdec0 : g_Wdec);
    const float* __restrict__ bias = (wsel == 0) ? g_benc : (wsel == 1 ? g_bdec0 : g_bdec);

    const int tid = threadIdx.x;
    const int lane = tid & 31, warp = tid >> 5;
    const int gid = lane >> 2, tig = lane & 3;
    const int warpM = warp >> 1, warpN = warp & 1;
    const int blockN = blockIdx.x * BN;
    const int blockM = blockIdx.y * BM;
    const int arow = tid >> 2;
    const int akq  = (tid & 3) * 4;

    float acc[4][8][4];
#pragma unroll
    for (int a = 0; a < 4; a++)
#pragma unroll
        for (int b = 0; b < 8; b++)
#pragma unroll
            for (int cc = 0; cc < 4; cc++) acc[a][b][cc] = 0.0f;

    float4 aReg[4];
    float4 bReg[2];

    auto fetch = [&](int t) {
        const int kg = t * BKT;
        const float* abase; int ld, koff;
        if (HAS_X && kg < DIN) { abase = x;   ld = DIN; koff = kg; }
        else                   { abase = hin; ld = HID; koff = kg - (HAS_X ? DIN : 0); }
#pragma unroll
        for (int i = 0; i < 4; i++)
            aReg[i] = *reinterpret_cast<const float4*>(abase + (size_t)(blockM + arow + i * 64) * ld + koff + akq);
#pragma unroll
        for (int i = 0; i < 2; i++)
            bReg[i] = *reinterpret_cast<const float4*>(W + (size_t)(blockN + arow + i * 64) * K + kg + akq);
    };
    auto store_smem = [&]() {
#pragma unroll
        for (int i = 0; i < 4; i++) {
            float* p = &As[arow + i * 64][akq];
            p[0] = to_tf32(aReg[i].x); p[1] = to_tf32(aReg[i].y);
            p[2] = to_tf32(aReg[i].z); p[3] = to_tf32(aReg[i].w);
        }
#pragma unroll
        for (int i = 0; i < 2; i++) {
            float* p = &Bs[arow + i * 64][akq];
            p[0] = bReg[i].x; p[1] = bReg[i].y; p[2] = bReg[i].z; p[3] = bReg[i].w;
        }
    };
    auto compute = [&]() {
#pragma unroll
        for (int kk = 0; kk < 2; kk++) {
            const int k0 = kk * 8;
            uint32_t aF[4][4];
#pragma unroll
            for (int mt = 0; mt < 4; mt++) {
                const int m = warpM * 64 + mt * 16;
                aF[mt][0] = __float_as_uint(As[m + gid    ][k0 + tig    ]);
                aF[mt][1] = __float_as_uint(As[m + gid + 8][k0 + tig    ]);
                aF[mt][2] = __float_as_uint(As[m + gid    ][k0 + tig + 4]);
                aF[mt][3] = __float_as_uint(As[m + gid + 8][k0 + tig + 4]);
            }
#pragma unroll
            for (int nt = 0; nt < 8; nt++) {
                const int nn = warpN * 64 + nt * 8;
                uint32_t bF[2];
                bF[0] = __float_as_uint(Bs[nn + gid][k0 + tig    ]);
                bF[1] = __float_as_uint(Bs[nn + gid][k0 + tig + 4]);
#pragma unroll
                for (int mt = 0; mt < 4; mt++) mma_tf32(acc[mt][nt], aF[mt], bF);
            }
        }
    };

    const int ktiles = K / BKT;
    fetch(0);
#pragma unroll 1
    for (int t = 0; t < ktiles; t++) {
        __syncthreads();
        store_smem();
        __syncthreads();
        if (t + 1 < ktiles) fetch(t + 1);
        compute();
    }

    // ---- fused LSTM cell epilogue (cols interleaved: 4u+{i,f,g,o}) ----
#pragma unroll
    for (int mt = 0; mt < 4; mt++) {
        const int r0 = blockM + warpM * 64 + mt * 16 + gid;
#pragma unroll
        for (int nt = 0; nt < 8; nt++) {
            const int cb = blockN + warpN * 64 + nt * 8;
            const float b0 = bias[cb + 2 * tig];
            const float b1 = bias[cb + 2 * tig + 1];
            float v0 = acc[mt][nt][0] + b0;
            float v1 = acc[mt][nt][1] + b1;
            float v2 = acc[mt][nt][2] + b0;
            float v3 = acc[mt][nt][3] + b1;
            const float p0 = __shfl_xor_sync(0xffffffffu, v0, 1);
            const float p1 = __shfl_xor_sync(0xffffffffu, v1, 1);
            const float p2 = __shfl_xor_sync(0xffffffffu, v2, 1);
            const float p3 = __shfl_xor_sync(0xffffffffu, v3, 1);
            const bool ev = (tig & 1) == 0;
            const int u = (cb >> 2) + (tig >> 1);
            const int row = ev ? r0 : (r0 + 8);
            const float gi = ev ? v0 : p2;
            const float gf = ev ? v1 : p3;
            const float gg = ev ? p0 : v2;
            const float go = ev ? p1 : v3;
            const size_t idx = (size_t)row * HID + u;
            const float cold = g_c[idx];
            const float si = sigmoid_f(gi);
            const float sf = sigmoid_f(gf);
            const float so = sigmoid_f(go);
            const float cn = fmaf(sf, cold, si * tanh_f(gg));
            const float hn = so * tanh_f(cn);
            g_c[idx] = cn;
            hout[idx] = hn;
            if (dec_t >= 0) g_Hdec[(size_t)dec_t * (BATCH * HID) + idx] = hn;
        }
    }
}

// ---------- final projection: out[96*2048, 64] = Hdec @ linW^T + lin_b ----------
__global__ __launch_bounds__(256, 1)
void proj_kernel(const float* __restrict__ linb, float* __restrict__ out) {
    __shared__ float As[128][SLDA];
    __shared__ float Bs[64][SLDA];
    const int tid = threadIdx.x;
    const int lane = tid & 31, warp = tid >> 5;
    const int gid = lane >> 2, tig = lane & 3;
    const int blockM = blockIdx.x * 128;
    const int arow = tid >> 2;
    const int akq  = (tid & 3) * 4;

    float acc[8][4];
#pragma unroll
    for (int b = 0; b < 8; b++)
#pragma unroll
        for (int cc = 0; cc < 4; cc++) acc[b][cc] = 0.0f;

    float4 aReg[2]; float4 bReg;
    auto fetch = [&](int t) {
        const int kg = t * BKT;
#pragma unroll
        for (int i = 0; i < 2; i++)
            aReg[i] = *reinterpret_cast<const float4*>(g_Hdec + (size_t)(blockM + arow + i * 64) * HID + kg + akq);
        bReg = *reinterpret_cast<const float4*>(g_linWt + (size_t)(arow & 63) * HID + kg + akq);
    };
    auto store_smem = [&]() {
#pragma unroll
        for (int i = 0; i < 2; i++) {
            float* p = &As[arow + i * 64][akq];
            p[0] = to_tf32(aReg[i].x); p[1] = to_tf32(aReg[i].y);
            p[2] = to_tf32(aReg[i].z); p[3] = to_tf32(aReg[i].w);
        }
        if (arow < 64) {
            float* p = &Bs[arow][akq];
            p[0] = bReg.x; p[1] = bReg.y; p[2] = bReg.z; p[3] = bReg.w;
        }
    };

    const int ktiles = HID / BKT;
    fetch(0);
#pragma unroll 1
    for (int t = 0; t < ktiles; t++) {
        __syncthreads();
        store_smem();
        __syncthreads();
        if (t + 1 < ktiles) fetch(t + 1);
#pragma unroll
        for (int kk = 0; kk < 2; kk++) {
            const int k0 = kk * 8;
            uint32_t aF[4];
            const int m = warp * 16;
            aF[0] = __float_as_uint(As[m + gid    ][k0 + tig    ]);
            aF[1] = __float_as_uint(As[m + gid + 8][k0 + tig    ]);
            aF[2] = __float_as_uint(As[m + gid    ][k0 + tig + 4]);
            aF[3] = __float_as_uint(As[m + gid + 8][k0 + tig + 4]);
#pragma unroll
            for (int nt = 0; nt < 8; nt++) {
                uint32_t bF[2];
                bF[0] = __float_as_uint(Bs[nt * 8 + gid][k0 + tig    ]);
                bF[1] = __float_as_uint(Bs[nt * 8 + gid][k0 + tig + 4]);
                mma_tf32(acc[nt], aF, bF);
            }
        }
    }

    const int r0 = blockM + warp * 16 + gid;
#pragma unroll
    for (int nt = 0; nt < 8; nt++) {
        const int c0 = nt * 8 + 2 * tig;
        const float b0 = linb[c0], b1 = linb[c0 + 1];
        out[(size_t)r0 * DIN + c0]           = acc[nt][0] + b0;
        out[(size_t)r0 * DIN + c0 + 1]       = acc[nt][1] + b1;
        out[(size_t)(r0 + 8) * DIN + c0]     = acc[nt][2] + b0;
        out[(size_t)(r0 + 8) * DIN + c0 + 1] = acc[nt][3] + b1;
    }
}

// ---------- launch ----------
extern "C" void kernel_launch(void* const* d_in, const int* in_sizes, int n_in,
                              void* d_out, int out_size) {
    const float* inputs = (const float*)d_in[0];
    const float* eWih = (const float*)d_in[1];
    const float* eWhh = (const float*)d_in[2];
    const float* ebih = (const float*)d_in[3];
    const float* ebhh = (const float*)d_in[4];
    const float* dWih = (const float*)d_in[5];
    const float* dWhh = (const float*)d_in[6];
    const float* dbih = (const float*)d_in[7];
    const float* dbhh = (const float*)d_in[8];
    const float* linW = (const float*)d_in[9];
    const float* linb = (const float*)d_in[10];
    float* out = (float*)d_out;

    prep_weights<<<G4, 256>>>(eWih, eWhh, ebih, ebhh, dWih, dWhh, dbih, dbhh, linW, linb);
    init_state<<<(BATCH * HID + 255) / 256, 256>>>();

    dim3 grid(G4 / BN, BATCH / BM);
    for (int t = 0; t < TIN; t++)
        lstm_step<KENC, true><<<grid, 256>>>(inputs + (size_t)t * BATCH * DIN, t & 1, 0, -1);
    for (int t = 0; t < TOUT; t++)
        lstm_step<KDEC, false><<<grid, 256>>>(nullptr, t & 1, t == 0 ? 1 : 2, t);

    proj_kernel<<<(TOUT * BATCH) / 128, 256>>>(linb, out);
}

// round 5
// speedup vs baseline: 1.4146x; 1.4146x over previous
#include <cuda_runtime.h>
#include <cuda_fp16.h>
#include <cstdint>

#define BATCH 2048
#define DIN 64
#define HID 512
#define G4 2048
#define KENC 576
#define KDEC 512
#define TIN 336
#define TOUT 96

#define BM 256
#define BN 128
#define BK 32                   // k-tile in halves
#define ASTR 40                 // padded smem row stride (halves), 80B = 16B-aligned
#define SROWS (BM + BN)         // 384 rows per stage (A then B)
#define SST (SROWS * ASTR)      // halves per stage
#define NSTAGE 4

// ---------- device scratch (16B-aligned for uint4 / cp.async) ----------
__device__ __align__(256) __half g_Wenc[G4 * KENC];
__device__ float  g_benc[G4];
__device__ __align__(256) __half g_Wdec0[G4 * KDEC];
__device__ float  g_bdec0[G4];
__device__ __align__(256) __half g_Wdec[G4 * KDEC];
__device__ float  g_bdec[G4];
__device__ __align__(256) __half g_linWt[DIN * HID];
__device__ __align__(256) __half g_x[(size_t)TIN * BATCH * DIN];
__device__ __align__(256) __half g_h0[BATCH * HID];
__device__ __align__(256) __half g_h1[BATCH * HID];
__device__ float  g_c[BATCH * HID];
__device__ __align__(256) __half g_Hdec[(size_t)TOUT * BATCH * HID];

// ---------- helpers ----------
__device__ __forceinline__ float rcp_fast(float x) {
    float y; asm("rcp.approx.f32 %0, %1;" : "=f"(y) : "f"(x)); return y;
}
__device__ __forceinline__ float sigmoid_f(float x) { return rcp_fast(1.0f + __expf(-x)); }
__device__ __forceinline__ float tanh_f(float x) { return 1.0f - 2.0f * rcp_fast(1.0f + __expf(2.0f * x)); }

__device__ __forceinline__ void mma_f16(float* c, const uint32_t* a, const uint32_t* b) {
    asm volatile(
        "mma.sync.aligned.m16n8k16.row.col.f32.f16.f16.f32 "
        "{%0,%1,%2,%3}, {%4,%5,%6,%7}, {%8,%9}, {%0,%1,%2,%3};"
        : "+f"(c[0]), "+f"(c[1]), "+f"(c[2]), "+f"(c[3])
        : "r"(a[0]), "r"(a[1]), "r"(a[2]), "r"(a[3]), "r"(b[0]), "r"(b[1]));
}

__device__ __forceinline__ void cp16(__half* smem_ptr, const __half* gptr) {
    uint32_t s = (uint32_t)__cvta_generic_to_shared(smem_ptr);
    asm volatile("cp.async.cg.shared.global [%0], [%1], 16;" :: "r"(s), "l"(gptr));
}
#define CP_COMMIT() asm volatile("cp.async.commit_group;" ::: "memory")
#define CP_WAIT2()  asm volatile("cp.async.wait_group 2;" ::: "memory")

// ---------- weight prep: gate interleave (n = 4u+gate) + decoder feedback fusion ----------
__global__ void prep_weights(const float* __restrict__ eWih, const float* __restrict__ eWhh,
                             const float* __restrict__ ebih, const float* __restrict__ ebhh,
                             const float* __restrict__ dWih, const float* __restrict__ dWhh,
                             const float* __restrict__ dbih, const float* __restrict__ dbhh,
                             const float* __restrict__ linW, const float* __restrict__ linb) {
    __shared__ float wih[DIN];
    const int n = blockIdx.x;
    const int u = n >> 2, g = n & 3;
    const int r = g * HID + u;

    for (int d = threadIdx.x; d < DIN; d += blockDim.x) wih[d] = dWih[r * DIN + d];
    __syncthreads();

    for (int k = threadIdx.x; k < KENC; k += blockDim.x) {
        float v = (k < DIN) ? eWih[r * DIN + k] : eWhh[r * HID + (k - DIN)];
        g_Wenc[n * KENC + k] = __float2half(v);
    }
    for (int k = threadIdx.x; k < KDEC; k += blockDim.x) {
        float w0 = dWhh[r * HID + k];
        g_Wdec0[n * KDEC + k] = __float2half(w0);
        float acc = w0;
#pragma unroll 8
        for (int d = 0; d < DIN; d++) acc += wih[d] * linW[d * HID + k];
        g_Wdec[n * KDEC + k] = __float2half(acc);
    }
    if (n < DIN) {
        for (int k = threadIdx.x; k < HID; k += blockDim.x)
            g_linWt[n * HID + k] = __float2half(linW[n * HID + k]);
    }
    if (threadIdx.x == 0) {
        g_benc[n] = ebih[r] + ebhh[r];
        float bd = dbih[r] + dbhh[r];
        g_bdec0[n] = bd;
        float acc = bd;
        for (int d = 0; d < DIN; d++) acc += wih[d] * linb[d];
        g_bdec[n] = acc;
    }
}

__global__ void convert_inputs(const float* __restrict__ inp) {
    size_t i = (size_t)blockIdx.x * blockDim.x + threadIdx.x;
    const size_t N = (size_t)TIN * BATCH * DIN;
    if (i < N) g_x[i] = __float2half(inp[i]);
}

__global__ void init_state() {
    int i = blockIdx.x * blockDim.x + threadIdx.x;
    if (i < BATCH * HID) { g_h0[i] = __float2half(0.0f); g_c[i] = 0.0f; }
}

// ---------- fused per-step GEMM + LSTM cell (fp16 mma, 4-stage cp.async) ----------
// NOTE: x pointer is computed INSIDE the kernel from the device symbol (t_x index);
// passing g_x+offset from host code silently reads the host shadow via ATS on GB300.
template <int K, bool HAS_X>
__global__ __launch_bounds__(256, 1)
void lstm_step(int t_x, int hsel, int wsel, int dec_t) {
    extern __shared__ __half sm[];   // [NSTAGE][SROWS][ASTR]

    const __half* __restrict__ x = HAS_X ? (g_x + (size_t)t_x * (BATCH * DIN)) : nullptr;
    const __half* __restrict__ hin  = hsel ? g_h1 : g_h0;
    __half* __restrict__       hout = hsel ? g_h0 : g_h1;
    const __half* __restrict__ W    = (wsel == 0) ? g_Wenc : (wsel == 1 ? g_Wdec0 : g_Wdec);
    const float*  __restrict__ bias = (wsel == 0) ? g_benc : (wsel == 1 ? g_bdec0 : g_bdec);

    const int tid = threadIdx.x;
    const int lane = tid & 31, warp = tid >> 5;
    const int gid = lane >> 2, tig = lane & 3;
    const int warpM = warp >> 1, warpN = warp & 1;
    const int blockN = blockIdx.x * BN;
    const int blockM = blockIdx.y * BM;
    const int arow = tid >> 2;          // 0..63
    const int acol = (tid & 3) * 8;     // halves (16B chunk)

    float acc[4][8][4];
#pragma unroll
    for (int a = 0; a < 4; a++)
#pragma unroll
        for (int b = 0; b < 8; b++)
#pragma unroll
            for (int cc = 0; cc < 4; cc++) acc[a][b][cc] = 0.0f;

    auto issue = [&](int t) {
        __half* base = sm + (t & 3) * SST;
        const int kg = t * BK;
        const __half* abase; int ld, koff;
        if (HAS_X && kg < DIN) { abase = x;   ld = DIN; koff = kg; }
        else                   { abase = hin; ld = HID; koff = kg - (HAS_X ? DIN : 0); }
#pragma unroll
        for (int i = 0; i < 4; i++) {
            const int row = arow + i * 64;
            cp16(base + row * ASTR + acol,
                 abase + (size_t)(blockM + row) * ld + koff + acol);
        }
#pragma unroll
        for (int i = 0; i < 2; i++) {
            const int row = arow + i * 64;
            cp16(base + (BM + row) * ASTR + acol,
                 W + (size_t)(blockN + row) * K + kg + acol);
        }
    };

    auto compute = [&](int s) {
        const __half* As = sm + s * SST;
        const __half* Bs = sm + s * SST + BM * ASTR;
#pragma unroll
        for (int kk = 0; kk < 2; kk++) {
            const int k0 = kk * 16;
            uint32_t aF[4][4];
#pragma unroll
            for (int mt = 0; mt < 4; mt++) {
                const int m = warpM * 64 + mt * 16 + gid;
                const __half* ap = As + m * ASTR + k0 + 2 * tig;
                aF[mt][0] = *reinterpret_cast<const uint32_t*>(ap);
                aF[mt][1] = *reinterpret_cast<const uint32_t*>(ap + 8 * ASTR);
                aF[mt][2] = *reinterpret_cast<const uint32_t*>(ap + 8);
                aF[mt][3] = *reinterpret_cast<const uint32_t*>(ap + 8 * ASTR + 8);
            }
#pragma unroll
            for (int nt = 0; nt < 8; nt++) {
                const int nn = warpN * 64 + nt * 8 + gid;
                const __half* bp = Bs + nn * ASTR + k0 + 2 * tig;
                uint32_t bF[2];
                bF[0] = *reinterpret_cast<const uint32_t*>(bp);
                bF[1] = *reinterpret_cast<const uint32_t*>(bp + 8);
#pragma unroll
                for (int mt = 0; mt < 4; mt++) mma_f16(acc[mt][nt], aF[mt], bF);
            }
        }
    };

    const int ktiles = K / BK;   // 18 (enc) / 16 (dec)
#pragma unroll
    for (int s = 0; s < NSTAGE - 1; s++) { issue(s); CP_COMMIT(); }

#pragma unroll 1
    for (int t = 0; t < ktiles; t++) {
        CP_WAIT2();            // stage t complete (one group per iter, incl. empty tail groups)
        __syncthreads();       // also protects stage (t-1)&3 from overwrite by issue below
        if (t + NSTAGE - 1 < ktiles) issue(t + NSTAGE - 1);
        CP_COMMIT();
        compute(t & 3);
    }

    // ---- fused LSTM cell epilogue (cols interleaved: 4u+{i,f,g,o}) ----
#pragma unroll
    for (int mt = 0; mt < 4; mt++) {
        const int r0 = blockM + warpM * 64 + mt * 16 + gid;
#pragma unroll
        for (int nt = 0; nt < 8; nt++) {
            const int cb = blockN + warpN * 64 + nt * 8;
            const float b0 = bias[cb + 2 * tig];
            const float b1 = bias[cb + 2 * tig + 1];
            float v0 = acc[mt][nt][0] + b0;
            float v1 = acc[mt][nt][1] + b1;
            float v2 = acc[mt][nt][2] + b0;
            float v3 = acc[mt][nt][3] + b1;
            const float p0 = __shfl_xor_sync(0xffffffffu, v0, 1);
            const float p1 = __shfl_xor_sync(0xffffffffu, v1, 1);
            const float p2 = __shfl_xor_sync(0xffffffffu, v2, 1);
            const float p3 = __shfl_xor_sync(0xffffffffu, v3, 1);
            const bool ev = (tig & 1) == 0;
            const int u = (cb >> 2) + (tig >> 1);
            const int row = ev ? r0 : (r0 + 8);
            const float gi = ev ? v0 : p2;
            const float gf = ev ? v1 : p3;
            const float gg = ev ? p0 : v2;
            const float go = ev ? p1 : v3;
            const size_t idx = (size_t)row * HID + u;
            const float cold = g_c[idx];
            const float si = sigmoid_f(gi);
            const float sf = sigmoid_f(gf);
            const float so = sigmoid_f(go);
            const float cn = fmaf(sf, cold, si * tanh_f(gg));
            const float hn = so * tanh_f(cn);
            g_c[idx] = cn;
            const __half hh = __float2half(hn);
            hout[idx] = hh;
            if (dec_t >= 0) g_Hdec[(size_t)dec_t * (BATCH * HID) + idx] = hh;
        }
    }
}

// ---------- final projection: out[96*2048, 64] = Hdec @ linW^T + lin_b (fp16 mma) ----------
__global__ __launch_bounds__(256, 1)
void proj_kernel(const float* __restrict__ linb, float* __restrict__ out) {
    __shared__ __half As[128][ASTR];
    __shared__ __half Bs[64][ASTR];
    const int tid = threadIdx.x;
    const int lane = tid & 31, warp = tid >> 5;
    const int gid = lane >> 2, tig = lane & 3;
    const int blockM = blockIdx.x * 128;
    const int arow = tid >> 2;
    const int acol = (tid & 3) * 8;

    float acc[8][4];
#pragma unroll
    for (int b = 0; b < 8; b++)
#pragma unroll
        for (int cc = 0; cc < 4; cc++) acc[b][cc] = 0.0f;

    uint4 aReg[2]; uint4 bReg;
    auto fetch = [&](int t) {
        const int kg = t * BK;
#pragma unroll
        for (int i = 0; i < 2; i++)
            aReg[i] = *reinterpret_cast<const uint4*>(g_Hdec + (size_t)(blockM + arow + i * 64) * HID + kg + acol);
        bReg = *reinterpret_cast<const uint4*>(g_linWt + (size_t)arow * HID + kg + acol);
    };
    auto store_smem = [&]() {
#pragma unroll
        for (int i = 0; i < 2; i++)
            *reinterpret_cast<uint4*>(&As[arow + i * 64][acol]) = aReg[i];
        if (arow < 64)
            *reinterpret_cast<uint4*>(&Bs[arow][acol]) = bReg;
    };

    const int ktiles = HID / BK;
    fetch(0);
#pragma unroll 1
    for (int t = 0; t < ktiles; t++) {
        __syncthreads();
        store_smem();
        __syncthreads();
        if (t + 1 < ktiles) fetch(t + 1);
#pragma unroll
        for (int kk = 0; kk < 2; kk++) {
            const int k0 = kk * 16;
            uint32_t aF[4];
            const int m = warp * 16 + gid;
            const __half* ap = &As[m][k0 + 2 * tig];
            aF[0] = *reinterpret_cast<const uint32_t*>(ap);
            aF[1] = *reinterpret_cast<const uint32_t*>(ap + 8 * ASTR);
            aF[2] = *reinterpret_cast<const uint32_t*>(ap + 8);
            aF[3] = *reinterpret_cast<const uint32_t*>(ap + 8 * ASTR + 8);
#pragma unroll
            for (int nt = 0; nt < 8; nt++) {
                const __half* bp = &Bs[nt * 8 + gid][k0 + 2 * tig];
                uint32_t bF[2];
                bF[0] = *reinterpret_cast<const uint32_t*>(bp);
                bF[1] = *reinterpret_cast<const uint32_t*>(bp + 8);
                mma_f16(acc[nt], aF, bF);
            }
        }
    }

    const int r0 = blockM + warp * 16 + gid;
#pragma unroll
    for (int nt = 0; nt < 8; nt++) {
        const int c0 = nt * 8 + 2 * tig;
        const float b0 = linb[c0], b1 = linb[c0 + 1];
        out[(size_t)r0 * DIN + c0]           = acc[nt][0] + b0;
        out[(size_t)r0 * DIN + c0 + 1]       = acc[nt][1] + b1;
        out[(size_t)(r0 + 8) * DIN + c0]     = acc[nt][2] + b0;
        out[(size_t)(r0 + 8) * DIN + c0 + 1] = acc[nt][3] + b1;
    }
}

// ---------- launch ----------
extern "C" void kernel_launch(void* const* d_in, const int* in_sizes, int n_in,
                              void* d_out, int out_size) {
    const float* inputs = (const float*)d_in[0];
    const float* eWih = (const float*)d_in[1];
    const float* eWhh = (const float*)d_in[2];
    const float* ebih = (const float*)d_in[3];
    const float* ebhh = (const float*)d_in[4];
    const float* dWih = (const float*)d_in[5];
    const float* dWhh = (const float*)d_in[6];
    const float* dbih = (const float*)d_in[7];
    const float* dbhh = (const float*)d_in[8];
    const float* linW = (const float*)d_in[9];
    const float* linb = (const float*)d_in[10];
    float* out = (float*)d_out;

    const int SMEM = NSTAGE * SST * (int)sizeof(__half);   // 4*384*40*2 = 122880
    cudaFuncSetAttribute(lstm_step<KENC, true>,  cudaFuncAttributeMaxDynamicSharedMemorySize, SMEM);
    cudaFuncSetAttribute(lstm_step<KDEC, false>, cudaFuncAttributeMaxDynamicSharedMemorySize, SMEM);

    prep_weights<<<G4, 256>>>(eWih, eWhh, ebih, ebhh, dWih, dWhh, dbih, dbhh, linW, linb);
    {
        const size_t N = (size_t)TIN * BATCH * DIN;
        convert_inputs<<<(int)((N + 255) / 256), 256>>>(inputs);
    }
    init_state<<<(BATCH * HID + 255) / 256, 256>>>();

    dim3 grid(G4 / BN, BATCH / BM);
    for (int t = 0; t < TIN; t++)
        lstm_step<KENC, true><<<grid, 256, SMEM>>>(t, t & 1, 0, -1);
    for (int t = 0; t < TOUT; t++)
        lstm_step<KDEC, false><<<grid, 256, SMEM>>>(0, t & 1, t == 0 ? 1 : 2, t);

    proj_kernel<<<(TOUT * BATCH) / 128, 256>>>(linb, out);
}

// round 6
// speedup vs baseline: 1.6084x; 1.1370x over previous
#include <cuda_runtime.h>
#include <cuda_fp16.h>
#include <cstdint>

#define BATCH 2048
#define DIN 64
#define HID 512
#define G4 2048
#define KENC 576
#define KDEC 512
#define TIN 336
#define TOUT 96

#define BM 256
#define BN 128
#define BK 32                   // k-tile in halves
#define ASTR 40                 // padded smem row stride (halves), 80B = 16B-aligned
#define SROWS (BM + BN)         // 384 rows per stage (A then B)
#define SST (SROWS * ASTR)      // halves per stage
#define NSTAGE 4
#define NTHREADS 512

// ---------- device scratch ----------
__device__ __align__(256) __half g_Wenc[G4 * KENC];
__device__ float  g_benc[G4];
__device__ __align__(256) __half g_Wdec0[G4 * KDEC];
__device__ float  g_bdec0[G4];
__device__ __align__(256) __half g_Wdec[G4 * KDEC];
__device__ float  g_bdec[G4];
__device__ __align__(256) __half g_linWt[DIN * HID];
__device__ __align__(256) __half g_x[(size_t)TIN * BATCH * DIN];
__device__ __align__(256) __half g_h0[BATCH * HID];
__device__ __align__(256) __half g_h1[BATCH * HID];
__device__ float  g_c[BATCH * HID];
__device__ __align__(256) __half g_Hdec[(size_t)TOUT * BATCH * HID];

// ---------- helpers ----------
__device__ __forceinline__ float rcp_fast(float x) {
    float y; asm("rcp.approx.f32 %0, %1;" : "=f"(y) : "f"(x)); return y;
}
__device__ __forceinline__ float sigmoid_f(float x) { return rcp_fast(1.0f + __expf(-x)); }
__device__ __forceinline__ float tanh_f(float x) { return 1.0f - 2.0f * rcp_fast(1.0f + __expf(2.0f * x)); }

__device__ __forceinline__ void mma_f16(float* c, const uint32_t* a, const uint32_t* b) {
    asm volatile(
        "mma.sync.aligned.m16n8k16.row.col.f32.f16.f16.f32 "
        "{%0,%1,%2,%3}, {%4,%5,%6,%7}, {%8,%9}, {%0,%1,%2,%3};"
        : "+f"(c[0]), "+f"(c[1]), "+f"(c[2]), "+f"(c[3])
        : "r"(a[0]), "r"(a[1]), "r"(a[2]), "r"(a[3]), "r"(b[0]), "r"(b[1]));
}

__device__ __forceinline__ void cp16(__half* smem_ptr, const __half* gptr) {
    uint32_t s = (uint32_t)__cvta_generic_to_shared(smem_ptr);
    asm volatile("cp.async.cg.shared.global [%0], [%1], 16;" :: "r"(s), "l"(gptr));
}
#define CP_COMMIT() asm volatile("cp.async.commit_group;" ::: "memory")
#define CP_WAIT2()  asm volatile("cp.async.wait_group 2;" ::: "memory")

// ---------- weight prep: gate interleave (n = 4u+gate) + decoder feedback fusion ----------
__global__ void prep_weights(const float* __restrict__ eWih, const float* __restrict__ eWhh,
                             const float* __restrict__ ebih, const float* __restrict__ ebhh,
                             const float* __restrict__ dWih, const float* __restrict__ dWhh,
                             const float* __restrict__ dbih, const float* __restrict__ dbhh,
                             const float* __restrict__ linW, const float* __restrict__ linb) {
    __shared__ float wih[DIN];
    const int n = blockIdx.x;
    const int u = n >> 2, g = n & 3;
    const int r = g * HID + u;

    for (int d = threadIdx.x; d < DIN; d += blockDim.x) wih[d] = dWih[r * DIN + d];
    __syncthreads();

    for (int k = threadIdx.x; k < KENC; k += blockDim.x) {
        float v = (k < DIN) ? eWih[r * DIN + k] : eWhh[r * HID + (k - DIN)];
        g_Wenc[n * KENC + k] = __float2half(v);
    }
    for (int k = threadIdx.x; k < KDEC; k += blockDim.x) {
        float w0 = dWhh[r * HID + k];
        g_Wdec0[n * KDEC + k] = __float2half(w0);
        float acc = w0;
#pragma unroll 8
        for (int d = 0; d < DIN; d++) acc += wih[d] * linW[d * HID + k];
        g_Wdec[n * KDEC + k] = __float2half(acc);
    }
    if (n < DIN) {
        for (int k = threadIdx.x; k < HID; k += blockDim.x)
            g_linWt[n * HID + k] = __float2half(linW[n * HID + k]);
    }
    if (threadIdx.x == 0) {
        g_benc[n] = ebih[r] + ebhh[r];
        float bd = dbih[r] + dbhh[r];
        g_bdec0[n] = bd;
        float acc = bd;
        for (int d = 0; d < DIN; d++) acc += wih[d] * linb[d];
        g_bdec[n] = acc;
    }
}

__global__ void convert_inputs(const float* __restrict__ inp) {
    size_t i = (size_t)blockIdx.x * blockDim.x + threadIdx.x;
    const size_t N = (size_t)TIN * BATCH * DIN;
    if (i < N) g_x[i] = __float2half(inp[i]);
}

__global__ void init_state() {
    int i = blockIdx.x * blockDim.x + threadIdx.x;
    if (i < BATCH * HID) { g_h0[i] = __float2half(0.0f); g_c[i] = 0.0f; }
}

// ---------- fused per-step GEMM + LSTM cell (fp16 mma, 4-stage cp.async, 16 warps) ----------
template <int K, bool HAS_X>
__global__ __launch_bounds__(NTHREADS, 1)
void lstm_step(int t_x, int hsel, int wsel, int dec_t) {
    extern __shared__ __half sm[];   // [NSTAGE][SROWS][ASTR]

    const __half* __restrict__ x = HAS_X ? (g_x + (size_t)t_x * (BATCH * DIN)) : nullptr;
    const __half* __restrict__ hin  = hsel ? g_h1 : g_h0;
    __half* __restrict__       hout = hsel ? g_h0 : g_h1;
    const __half* __restrict__ W    = (wsel == 0) ? g_Wenc : (wsel == 1 ? g_Wdec0 : g_Wdec);
    const float*  __restrict__ bias = (wsel == 0) ? g_benc : (wsel == 1 ? g_bdec0 : g_bdec);

    const int tid = threadIdx.x;
    const int lane = tid & 31, warp = tid >> 5;       // 16 warps
    const int gid = lane >> 2, tig = lane & 3;
    const int warpM = warp >> 1, warpN = warp & 1;    // warpM 0..7, warpN 0..1
    const int blockN = blockIdx.x * BN;
    const int blockM = blockIdx.y * BM;
    const int arow = tid >> 2;          // 0..127
    const int acol = (tid & 3) * 8;     // halves (16B chunk)

    float acc[2][8][4];
#pragma unroll
    for (int a = 0; a < 2; a++)
#pragma unroll
        for (int b = 0; b < 8; b++)
#pragma unroll
            for (int cc = 0; cc < 4; cc++) acc[a][b][cc] = 0.0f;

    auto issue = [&](int t) {
        __half* base = sm + (t & 3) * SST;
        const int kg = t * BK;
        const __half* abase; int ld, koff;
        if (HAS_X && kg < DIN) { abase = x;   ld = DIN; koff = kg; }
        else                   { abase = hin; ld = HID; koff = kg - (HAS_X ? DIN : 0); }
#pragma unroll
        for (int i = 0; i < 2; i++) {     // A: 256 rows, 2 per thread
            const int row = arow + i * 128;
            cp16(base + row * ASTR + acol,
                 abase + (size_t)(blockM + row) * ld + koff + acol);
        }
        {                                  // B: 128 rows, 1 per thread
            cp16(base + (BM + arow) * ASTR + acol,
                 W + (size_t)(blockN + arow) * K + kg + acol);
        }
    };

    auto compute = [&](int s) {
        const __half* As = sm + s * SST;
        const __half* Bs = sm + s * SST + BM * ASTR;
#pragma unroll
        for (int kk = 0; kk < 2; kk++) {
            const int k0 = kk * 16;
            uint32_t aF[2][4];
#pragma unroll
            for (int mt = 0; mt < 2; mt++) {
                const int m = warpM * 32 + mt * 16 + gid;
                const __half* ap = As + m * ASTR + k0 + 2 * tig;
                aF[mt][0] = *reinterpret_cast<const uint32_t*>(ap);
                aF[mt][1] = *reinterpret_cast<const uint32_t*>(ap + 8 * ASTR);
                aF[mt][2] = *reinterpret_cast<const uint32_t*>(ap + 8);
                aF[mt][3] = *reinterpret_cast<const uint32_t*>(ap + 8 * ASTR + 8);
            }
#pragma unroll
            for (int nt = 0; nt < 8; nt++) {
                const int nn = warpN * 64 + nt * 8 + gid;
                const __half* bp = Bs + nn * ASTR + k0 + 2 * tig;
                uint32_t bF[2];
                bF[0] = *reinterpret_cast<const uint32_t*>(bp);
                bF[1] = *reinterpret_cast<const uint32_t*>(bp + 8);
#pragma unroll
                for (int mt = 0; mt < 2; mt++) mma_f16(acc[mt][nt], aF[mt], bF);
            }
        }
    };

    const int ktiles = K / BK;   // 18 (enc) / 16 (dec)
#pragma unroll
    for (int s = 0; s < NSTAGE - 1; s++) { issue(s); CP_COMMIT(); }

#pragma unroll 1
    for (int t = 0; t < ktiles; t++) {
        CP_WAIT2();
        __syncthreads();
        if (t + NSTAGE - 1 < ktiles) issue(t + NSTAGE - 1);
        CP_COMMIT();
        compute(t & 3);
    }

    // ---- fused LSTM cell epilogue (cols interleaved: 4u+{i,f,g,o}) ----
#pragma unroll
    for (int mt = 0; mt < 2; mt++) {
        const int r0 = blockM + warpM * 32 + mt * 16 + gid;
#pragma unroll
        for (int nt = 0; nt < 8; nt++) {
            const int cb = blockN + warpN * 64 + nt * 8;
            const float b0 = bias[cb + 2 * tig];
            const float b1 = bias[cb + 2 * tig + 1];
            float v0 = acc[mt][nt][0] + b0;
            float v1 = acc[mt][nt][1] + b1;
            float v2 = acc[mt][nt][2] + b0;
            float v3 = acc[mt][nt][3] + b1;
            const float p0 = __shfl_xor_sync(0xffffffffu, v0, 1);
            const float p1 = __shfl_xor_sync(0xffffffffu, v1, 1);
            const float p2 = __shfl_xor_sync(0xffffffffu, v2, 1);
            const float p3 = __shfl_xor_sync(0xffffffffu, v3, 1);
            const bool ev = (tig & 1) == 0;
            const int u = (cb >> 2) + (tig >> 1);
            const int row = ev ? r0 : (r0 + 8);
            const float gi = ev ? v0 : p2;
            const float gf = ev ? v1 : p3;
            const float gg = ev ? p0 : v2;
            const float go = ev ? p1 : v3;
            const size_t idx = (size_t)row * HID + u;
            const float cold = g_c[idx];
            const float si = sigmoid_f(gi);
            const float sf = sigmoid_f(gf);
            const float so = sigmoid_f(go);
            const float cn = fmaf(sf, cold, si * tanh_f(gg));
            const float hn = so * tanh_f(cn);
            g_c[idx] = cn;
            const __half hh = __float2half(hn);
            hout[idx] = hh;
            if (dec_t >= 0) g_Hdec[(size_t)dec_t * (BATCH * HID) + idx] = hh;
        }
    }
}

// ---------- final projection: out[96*2048, 64] = Hdec @ linW^T + lin_b (fp16 mma) ----------
__global__ __launch_bounds__(256, 1)
void proj_kernel(const float* __restrict__ linb, float* __restrict__ out) {
    __shared__ __half As[128][ASTR];
    __shared__ __half Bs[64][ASTR];
    const int tid = threadIdx.x;
    const int lane = tid & 31, warp = tid >> 5;
    const int gid = lane >> 2, tig = lane & 3;
    const int blockM = blockIdx.x * 128;
    const int arow = tid >> 2;
    const int acol = (tid & 3) * 8;

    float acc[8][4];
#pragma unroll
    for (int b = 0; b < 8; b++)
#pragma unroll
        for (int cc = 0; cc < 4; cc++) acc[b][cc] = 0.0f;

    uint4 aReg[2]; uint4 bReg;
    auto fetch = [&](int t) {
        const int kg = t * BK;
#pragma unroll
        for (int i = 0; i < 2; i++)
            aReg[i] = *reinterpret_cast<const uint4*>(g_Hdec + (size_t)(blockM + arow + i * 64) * HID + kg + acol);
        bReg = *reinterpret_cast<const uint4*>(g_linWt + (size_t)arow * HID + kg + acol);
    };
    auto store_smem = [&]() {
#pragma unroll
        for (int i = 0; i < 2; i++)
            *reinterpret_cast<uint4*>(&As[arow + i * 64][acol]) = aReg[i];
        if (arow < 64)
            *reinterpret_cast<uint4*>(&Bs[arow][acol]) = bReg;
    };

    const int ktiles = HID / BK;
    fetch(0);
#pragma unroll 1
    for (int t = 0; t < ktiles; t++) {
        __syncthreads();
        store_smem();
        __syncthreads();
        if (t + 1 < ktiles) fetch(t + 1);
#pragma unroll
        for (int kk = 0; kk < 2; kk++) {
            const int k0 = kk * 16;
            uint32_t aF[4];
            const int m = warp * 16 + gid;
            const __half* ap = &As[m][k0 + 2 * tig];
            aF[0] = *reinterpret_cast<const uint32_t*>(ap);
            aF[1] = *reinterpret_cast<const uint32_t*>(ap + 8 * ASTR);
            aF[2] = *reinterpret_cast<const uint32_t*>(ap + 8);
            aF[3] = *reinterpret_cast<const uint32_t*>(ap + 8 * ASTR + 8);
#pragma unroll
            for (int nt = 0; nt < 8; nt++) {
                const __half* bp = &Bs[nt * 8 + gid][k0 + 2 * tig];
                uint32_t bF[2];
                bF[0] = *reinterpret_cast<const uint32_t*>(bp);
                bF[1] = *reinterpret_cast<const uint32_t*>(bp + 8);
                mma_f16(acc[nt], aF, bF);
            }
        }
    }

    const int r0 = blockM + warp * 16 + gid;
#pragma unroll
    for (int nt = 0; nt < 8; nt++) {
        const int c0 = nt * 8 + 2 * tig;
        const float b0 = linb[c0], b1 = linb[c0 + 1];
        out[(size_t)r0 * DIN + c0]           = acc[nt][0] + b0;
        out[(size_t)r0 * DIN + c0 + 1]       = acc[nt][1] + b1;
        out[(size_t)(r0 + 8) * DIN + c0]     = acc[nt][2] + b0;
        out[(size_t)(r0 + 8) * DIN + c0 + 1] = acc[nt][3] + b1;
    }
}

// ---------- launch ----------
extern "C" void kernel_launch(void* const* d_in, const int* in_sizes, int n_in,
                              void* d_out, int out_size) {
    const float* inputs = (const float*)d_in[0];
    const float* eWih = (const float*)d_in[1];
    const float* eWhh = (const float*)d_in[2];
    const float* ebih = (const float*)d_in[3];
    const float* ebhh = (const float*)d_in[4];
    const float* dWih = (const float*)d_in[5];
    const float* dWhh = (const float*)d_in[6];
    const float* dbih = (const float*)d_in[7];
    const float* dbhh = (const float*)d_in[8];
    const float* linW = (const float*)d_in[9];
    const float* linb = (const float*)d_in[10];
    float* out = (float*)d_out;

    const int SMEM = NSTAGE * SST * (int)sizeof(__half);   // 122880
    cudaFuncSetAttribute(lstm_step<KENC, true>,  cudaFuncAttributeMaxDynamicSharedMemorySize, SMEM);
    cudaFuncSetAttribute(lstm_step<KDEC, false>, cudaFuncAttributeMaxDynamicSharedMemorySize, SMEM);

    prep_weights<<<G4, 256>>>(eWih, eWhh, ebih, ebhh, dWih, dWhh, dbih, dbhh, linW, linb);
    {
        const size_t N = (size_t)TIN * BATCH * DIN;
        convert_inputs<<<(int)((N + 255) / 256), 256>>>(inputs);
    }
    init_state<<<(BATCH * HID + 255) / 256, 256>>>();

    dim3 grid(G4 / BN, BATCH / BM);
    for (int t = 0; t < TIN; t++)
        lstm_step<KENC, true><<<grid, NTHREADS, SMEM>>>(t, t & 1, 0, -1);
    for (int t = 0; t < TOUT; t++)
        lstm_step<KDEC, false><<<grid, NTHREADS, SMEM>>>(0, t & 1, t == 0 ? 1 : 2, t);

    proj_kernel<<<(TOUT * BATCH) / 128, 256>>>(linb, out);
}

// round 7
// speedup vs baseline: 1.7345x; 1.0784x over previous
#include <cuda_runtime.h>
#include <cuda_fp16.h>
#include <cstdint>

#define BATCH 2048
#define DIN 64
#define HID 512
#define G4 2048
#define KENC 576
#define KDEC 512
#define TIN 336
#define TOUT 96

#define BM 128
#define BN 128
#define BK 32                   // k-tile in halves
#define ASTR 40                 // padded smem row stride (halves), 80B
#define SROWS (BM + BN)         // 256 rows per stage (A then B)
#define SST (SROWS * ASTR)      // halves per stage
#define NSTAGE 4
#define NTHREADS 256

// ---------- device scratch ----------
__device__ __align__(256) __half g_Wenc[G4 * KENC];
__device__ float  g_benc[G4];
__device__ __align__(256) __half g_Wdec0[G4 * KDEC];
__device__ float  g_bdec0[G4];
__device__ __align__(256) __half g_Wdec[G4 * KDEC];
__device__ float  g_bdec[G4];
__device__ __align__(256) __half g_linWt[DIN * HID];
__device__ __align__(256) __half g_x[(size_t)TIN * BATCH * DIN];
__device__ __align__(256) __half g_h0[BATCH * HID];
__device__ __align__(256) __half g_h1[BATCH * HID];
__device__ float  g_c[BATCH * HID];
__device__ __align__(256) __half g_Hdec[(size_t)TOUT * BATCH * HID];

// ---------- helpers ----------
__device__ __forceinline__ float rcp_fast(float x) {
    float y; asm("rcp.approx.f32 %0, %1;" : "=f"(y) : "f"(x)); return y;
}
__device__ __forceinline__ float sigmoid_f(float x) { return rcp_fast(1.0f + __expf(-x)); }
__device__ __forceinline__ float tanh_f(float x) { return 1.0f - 2.0f * rcp_fast(1.0f + __expf(2.0f * x)); }

__device__ __forceinline__ void mma_f16(float* c, const uint32_t* a, const uint32_t* b) {
    asm volatile(
        "mma.sync.aligned.m16n8k16.row.col.f32.f16.f16.f32 "
        "{%0,%1,%2,%3}, {%4,%5,%6,%7}, {%8,%9}, {%0,%1,%2,%3};"
        : "+f"(c[0]), "+f"(c[1]), "+f"(c[2]), "+f"(c[3])
        : "r"(a[0]), "r"(a[1]), "r"(a[2]), "r"(a[3]), "r"(b[0]), "r"(b[1]));
}

__device__ __forceinline__ void ldsm_x4(uint32_t* r, uint32_t addr) {
    asm volatile("ldmatrix.sync.aligned.m8n8.x4.shared.b16 {%0,%1,%2,%3}, [%4];"
                 : "=r"(r[0]), "=r"(r[1]), "=r"(r[2]), "=r"(r[3]) : "r"(addr));
}

__device__ __forceinline__ void cp16(__half* smem_ptr, const __half* gptr) {
    uint32_t s = (uint32_t)__cvta_generic_to_shared(smem_ptr);
    asm volatile("cp.async.cg.shared.global [%0], [%1], 16;" :: "r"(s), "l"(gptr));
}
#define CP_COMMIT() asm volatile("cp.async.commit_group;" ::: "memory")
#define CP_WAIT2()  asm volatile("cp.async.wait_group 2;" ::: "memory")

// ---------- weight prep: gate interleave (n = 4u+gate) + decoder feedback fusion ----------
__global__ void prep_weights(const float* __restrict__ eWih, const float* __restrict__ eWhh,
                             const float* __restrict__ ebih, const float* __restrict__ ebhh,
                             const float* __restrict__ dWih, const float* __restrict__ dWhh,
                             const float* __restrict__ dbih, const float* __restrict__ dbhh,
                             const float* __restrict__ linW, const float* __restrict__ linb) {
    __shared__ float wih[DIN];
    const int n = blockIdx.x;
    const int u = n >> 2, g = n & 3;
    const int r = g * HID + u;

    for (int d = threadIdx.x; d < DIN; d += blockDim.x) wih[d] = dWih[r * DIN + d];
    __syncthreads();

    for (int k = threadIdx.x; k < KENC; k += blockDim.x) {
        float v = (k < DIN) ? eWih[r * DIN + k] : eWhh[r * HID + (k - DIN)];
        g_Wenc[n * KENC + k] = __float2half(v);
    }
    for (int k = threadIdx.x; k < KDEC; k += blockDim.x) {
        float w0 = dWhh[r * HID + k];
        g_Wdec0[n * KDEC + k] = __float2half(w0);
        float acc = w0;
#pragma unroll 8
        for (int d = 0; d < DIN; d++) acc += wih[d] * linW[d * HID + k];
        g_Wdec[n * KDEC + k] = __float2half(acc);
    }
    if (n < DIN) {
        for (int k = threadIdx.x; k < HID; k += blockDim.x)
            g_linWt[n * HID + k] = __float2half(linW[n * HID + k]);
    }
    if (threadIdx.x == 0) {
        g_benc[n] = ebih[r] + ebhh[r];
        float bd = dbih[r] + dbhh[r];
        g_bdec0[n] = bd;
        float acc = bd;
        for (int d = 0; d < DIN; d++) acc += wih[d] * linb[d];
        g_bdec[n] = acc;
    }
}

__global__ void convert_inputs(const float* __restrict__ inp) {
    size_t i = (size_t)blockIdx.x * blockDim.x + threadIdx.x;
    const size_t N = (size_t)TIN * BATCH * DIN;
    if (i < N) g_x[i] = __float2half(inp[i]);
}

__global__ void init_state() {
    int i = blockIdx.x * blockDim.x + threadIdx.x;
    if (i < BATCH * HID) { g_h0[i] = __float2half(0.0f); g_c[i] = 0.0f; }
}

// ---------- fused per-step GEMM + LSTM cell (fp16 mma, cp.async, ldmatrix, 2 CTA/SM) ----------
template <int K, bool HAS_X>
__global__ __launch_bounds__(NTHREADS, 2)
void lstm_step(int t_x, int hsel, int wsel, int dec_t) {
    extern __shared__ __half sm[];   // [NSTAGE][SROWS][ASTR]

    const __half* __restrict__ x = HAS_X ? (g_x + (size_t)t_x * (BATCH * DIN)) : nullptr;
    const __half* __restrict__ hin  = hsel ? g_h1 : g_h0;
    __half* __restrict__       hout = hsel ? g_h0 : g_h1;
    const __half* __restrict__ W    = (wsel == 0) ? g_Wenc : (wsel == 1 ? g_Wdec0 : g_Wdec);
    const float*  __restrict__ bias = (wsel == 0) ? g_benc : (wsel == 1 ? g_bdec0 : g_bdec);

    const int tid = threadIdx.x;
    const int lane = tid & 31, warp = tid >> 5;       // 8 warps
    const int gid = lane >> 2, tig = lane & 3;
    const int warpM = warp >> 1, warpN = warp & 1;    // warpM 0..3 (32 rows), warpN 0..1 (64 cols)
    const int blockN = blockIdx.x * BN;
    const int blockM = blockIdx.y * BM;
    const int arow = tid >> 2;          // 0..63
    const int acol = (tid & 3) * 8;     // halves (16B chunk)

    const uint32_t smu = (uint32_t)__cvta_generic_to_shared(sm);
    // per-lane ldmatrix offsets (halves)
    const int a_off = ((lane & 7) + 8 * ((lane >> 3) & 1)) * ASTR + 8 * ((lane >> 4) & 1);
    const int b_off = ((lane & 7) + 8 * ((lane >> 4) & 1)) * ASTR + 8 * ((lane >> 3) & 1);

    float acc[2][8][4];
#pragma unroll
    for (int a = 0; a < 2; a++)
#pragma unroll
        for (int b = 0; b < 8; b++)
#pragma unroll
            for (int cc = 0; cc < 4; cc++) acc[a][b][cc] = 0.0f;

    auto issue = [&](int t) {
        __half* base = sm + (t & 3) * SST;
        const int kg = t * BK;
        const __half* abase; int ld, koff;
        if (HAS_X && kg < DIN) { abase = x;   ld = DIN; koff = kg; }
        else                   { abase = hin; ld = HID; koff = kg - (HAS_X ? DIN : 0); }
#pragma unroll
        for (int i = 0; i < 2; i++) {     // A: 128 rows
            const int row = arow + i * 64;
            cp16(base + row * ASTR + acol,
                 abase + (size_t)(blockM + row) * ld + koff + acol);
        }
#pragma unroll
        for (int i = 0; i < 2; i++) {     // B: 128 rows
            const int row = arow + i * 64;
            cp16(base + (BM + row) * ASTR + acol,
                 W + (size_t)(blockN + row) * K + kg + acol);
        }
    };

    auto compute = [&](int s) {
        const uint32_t As = smu + (uint32_t)(s * SST) * 2u;
        const uint32_t Bs = As + (uint32_t)(BM * ASTR) * 2u;
#pragma unroll
        for (int kk = 0; kk < 2; kk++) {
            const int k0 = kk * 16;
            uint32_t aF[2][4];
#pragma unroll
            for (int mt = 0; mt < 2; mt++) {
                const int m0 = warpM * 32 + mt * 16;
                ldsm_x4(aF[mt], As + (uint32_t)((m0 * ASTR + k0 + a_off) * 2));
            }
            uint32_t bF[8][2];
#pragma unroll
            for (int ntp = 0; ntp < 4; ntp++) {
                const int n0 = warpN * 64 + ntp * 16;
                uint32_t r[4];
                ldsm_x4(r, Bs + (uint32_t)((n0 * ASTR + k0 + b_off) * 2));
                bF[2 * ntp][0] = r[0]; bF[2 * ntp][1] = r[1];
                bF[2 * ntp + 1][0] = r[2]; bF[2 * ntp + 1][1] = r[3];
            }
#pragma unroll
            for (int nt = 0; nt < 8; nt++)
#pragma unroll
                for (int mt = 0; mt < 2; mt++) mma_f16(acc[mt][nt], aF[mt], bF[nt]);
        }
    };

    const int ktiles = K / BK;   // 18 (enc) / 16 (dec)
#pragma unroll
    for (int s = 0; s < NSTAGE - 1; s++) { issue(s); CP_COMMIT(); }

#pragma unroll 1
    for (int t = 0; t < ktiles; t++) {
        CP_WAIT2();
        __syncthreads();
        if (t + NSTAGE - 1 < ktiles) issue(t + NSTAGE - 1);
        CP_COMMIT();
        compute(t & 3);
    }

    // ---- fused LSTM cell epilogue (cols interleaved: 4u+{i,f,g,o}) ----
#pragma unroll
    for (int mt = 0; mt < 2; mt++) {
        const int r0 = blockM + warpM * 32 + mt * 16 + gid;
#pragma unroll
        for (int nt = 0; nt < 8; nt++) {
            const int cb = blockN + warpN * 64 + nt * 8;
            const float b0 = bias[cb + 2 * tig];
            const float b1 = bias[cb + 2 * tig + 1];
            float v0 = acc[mt][nt][0] + b0;
            float v1 = acc[mt][nt][1] + b1;
            float v2 = acc[mt][nt][2] + b0;
            float v3 = acc[mt][nt][3] + b1;
            const float p0 = __shfl_xor_sync(0xffffffffu, v0, 1);
            const float p1 = __shfl_xor_sync(0xffffffffu, v1, 1);
            const float p2 = __shfl_xor_sync(0xffffffffu, v2, 1);
            const float p3 = __shfl_xor_sync(0xffffffffu, v3, 1);
            const bool ev = (tig & 1) == 0;
            const int u = (cb >> 2) + (tig >> 1);
            const int row = ev ? r0 : (r0 + 8);
            const float gi = ev ? v0 : p2;
            const float gf = ev ? v1 : p3;
            const float gg = ev ? p0 : v2;
            const float go = ev ? p1 : v3;
            const size_t idx = (size_t)row * HID + u;
            const float cold = g_c[idx];
            const float si = sigmoid_f(gi);
            const float sf = sigmoid_f(gf);
            const float so = sigmoid_f(go);
            const float cn = fmaf(sf, cold, si * tanh_f(gg));
            const float hn = so * tanh_f(cn);
            g_c[idx] = cn;
            const __half hh = __float2half(hn);
            hout[idx] = hh;
            if (dec_t >= 0) g_Hdec[(size_t)dec_t * (BATCH * HID) + idx] = hh;
        }
    }
}

// ---------- final projection: out[96*2048, 64] = Hdec @ linW^T + lin_b (fp16 mma) ----------
__global__ __launch_bounds__(256, 1)
void proj_kernel(const float* __restrict__ linb, float* __restrict__ out) {
    __shared__ __half As[128][ASTR];
    __shared__ __half Bs[64][ASTR];
    const int tid = threadIdx.x;
    const int lane = tid & 31, warp = tid >> 5;
    const int gid = lane >> 2, tig = lane & 3;
    const int blockM = blockIdx.x * 128;
    const int arow = tid >> 2;
    const int acol = (tid & 3) * 8;

    float acc[8][4];
#pragma unroll
    for (int b = 0; b < 8; b++)
#pragma unroll
        for (int cc = 0; cc < 4; cc++) acc[b][cc] = 0.0f;

    uint4 aReg[2]; uint4 bReg;
    auto fetch = [&](int t) {
        const int kg = t * BK;
#pragma unroll
        for (int i = 0; i < 2; i++)
            aReg[i] = *reinterpret_cast<const uint4*>(g_Hdec + (size_t)(blockM + arow + i * 64) * HID + kg + acol);
        bReg = *reinterpret_cast<const uint4*>(g_linWt + (size_t)arow * HID + kg + acol);
    };
    auto store_smem = [&]() {
#pragma unroll
        for (int i = 0; i < 2; i++)
            *reinterpret_cast<uint4*>(&As[arow + i * 64][acol]) = aReg[i];
        if (arow < 64)
            *reinterpret_cast<uint4*>(&Bs[arow][acol]) = bReg;
    };

    const int ktiles = HID / BK;
    fetch(0);
#pragma unroll 1
    for (int t = 0; t < ktiles; t++) {
        __syncthreads();
        store_smem();
        __syncthreads();
        if (t + 1 < ktiles) fetch(t + 1);
#pragma unroll
        for (int kk = 0; kk < 2; kk++) {
            const int k0 = kk * 16;
            uint32_t aF[4];
            const int m = warp * 16 + gid;
            const __half* ap = &As[m][k0 + 2 * tig];
            aF[0] = *reinterpret_cast<const uint32_t*>(ap);
            aF[1] = *reinterpret_cast<const uint32_t*>(ap + 8 * ASTR);
            aF[2] = *reinterpret_cast<const uint32_t*>(ap + 8);
            aF[3] = *reinterpret_cast<const uint32_t*>(ap + 8 * ASTR + 8);
#pragma unroll
            for (int nt = 0; nt < 8; nt++) {
                const __half* bp = &Bs[nt * 8 + gid][k0 + 2 * tig];
                uint32_t bF[2];
                bF[0] = *reinterpret_cast<const uint32_t*>(bp);
                bF[1] = *reinterpret_cast<const uint32_t*>(bp + 8);
                mma_f16(acc[nt], aF, bF);
            }
        }
    }

    const int r0 = blockM + warp * 16 + gid;
#pragma unroll
    for (int nt = 0; nt < 8; nt++) {
        const int c0 = nt * 8 + 2 * tig;
        const float b0 = linb[c0], b1 = linb[c0 + 1];
        out[(size_t)r0 * DIN + c0]           = acc[nt][0] + b0;
        out[(size_t)r0 * DIN + c0 + 1]       = acc[nt][1] + b1;
        out[(size_t)(r0 + 8) * DIN + c0]     = acc[nt][2] + b0;
        out[(size_t)(r0 + 8) * DIN + c0 + 1] = acc[nt][3] + b1;
    }
}

// ---------- launch ----------
extern "C" void kernel_launch(void* const* d_in, const int* in_sizes, int n_in,
                              void* d_out, int out_size) {
    const float* inputs = (const float*)d_in[0];
    const float* eWih = (const float*)d_in[1];
    const float* eWhh = (const float*)d_in[2];
    const float* ebih = (const float*)d_in[3];
    const float* ebhh = (const float*)d_in[4];
    const float* dWih = (const float*)d_in[5];
    const float* dWhh = (const float*)d_in[6];
    const float* dbih = (const float*)d_in[7];
    const float* dbhh = (const float*)d_in[8];
    const float* linW = (const float*)d_in[9];
    const float* linb = (const float*)d_in[10];
    float* out = (float*)d_out;

    const int SMEM = NSTAGE * SST * (int)sizeof(__half);   // 4*256*40*2 = 81920
    cudaFuncSetAttribute(lstm_step<KENC, true>,  cudaFuncAttributeMaxDynamicSharedMemorySize, SMEM);
    cudaFuncSetAttribute(lstm_step<KDEC, false>, cudaFuncAttributeMaxDynamicSharedMemorySize, SMEM);

    prep_weights<<<G4, 256>>>(eWih, eWhh, ebih, ebhh, dWih, dWhh, dbih, dbhh, linW, linb);
    {
        const size_t N = (size_t)TIN * BATCH * DIN;
        convert_inputs<<<(int)((N + 255) / 256), 256>>>(inputs);
    }
    init_state<<<(BATCH * HID + 255) / 256, 256>>>();

    dim3 grid(G4 / BN, BATCH / BM);   // 16 x 16 = 256 CTAs
    for (int t = 0; t < TIN; t++)
        lstm_step<KENC, true><<<grid, NTHREADS, SMEM>>>(t, t & 1, 0, -1);
    for (int t = 0; t < TOUT; t++)
        lstm_step<KDEC, false><<<grid, NTHREADS, SMEM>>>(0, t & 1, t == 0 ? 1 : 2, t);

    proj_kernel<<<(TOUT * BATCH) / 128, 256>>>(linb, out);
}